// round 15
// baseline (speedup 1.0000x reference)
#include <cuda_runtime.h>
#include <cuda_bf16.h>
#include <math.h>
#include <stdint.h>

#define BB 64
#define TT 31
#define EE 512
#define HH 1024
#define GG 4096
#define VV 32000
#define MPAD 2048
typedef __nv_bfloat16 bf;

__device__ __align__(16) bf g_ctxH[BB * HH], g_ctxL[BB * HH];
__device__ __align__(16) bf g_embH[(size_t)TT * BB * EE], g_embL[(size_t)TT * BB * EE];
__device__ __align__(16) bf g_hsH[(size_t)MPAD * HH], g_hsL[(size_t)MPAD * HH];
__device__ __align__(16) bf g_h0H[BB * HH], g_h0L[BB * HH];
__device__ float g_gbias[BB * GG];
__device__ float g_gx[(size_t)TT * BB * GG];
__device__ float g_c[BB * HH];

// ---------------------------------------------------------------------------
#define CP16(dst, src) asm volatile("cp.async.ca.shared.global [%0], [%1], 16;" :: "r"(dst), "l"(src) : "memory")
#define CP_COMMIT() asm volatile("cp.async.commit_group;" ::: "memory")
#define CP_WAIT0() asm volatile("cp.async.wait_group 0;" ::: "memory")
#define CP_WAIT1() asm volatile("cp.async.wait_group 1;" ::: "memory")

__device__ __forceinline__ unsigned s2u(const void* p) {
    return (unsigned)__cvta_generic_to_shared(p);
}
__device__ __forceinline__ void mma_bf16(float c[4], const unsigned a[4], const unsigned b[2]) {
    asm("mma.sync.aligned.m16n8k16.row.col.f32.bf16.bf16.f32 "
        "{%0,%1,%2,%3},{%4,%5,%6,%7},{%8,%9},{%0,%1,%2,%3};"
        : "+f"(c[0]), "+f"(c[1]), "+f"(c[2]), "+f"(c[3])
        : "r"(a[0]), "r"(a[1]), "r"(a[2]), "r"(a[3]), "r"(b[0]), "r"(b[1]));
}
__device__ __forceinline__ void split2(float x, float y, unsigned& hi, unsigned& lo) {
    bf hx = __float2bfloat16(x), hy = __float2bfloat16(y);
    __nv_bfloat162 H = __halves2bfloat162(hx, hy);
    __nv_bfloat162 L = __halves2bfloat162(__float2bfloat16(x - __bfloat162float(hx)),
                                          __float2bfloat16(y - __bfloat162float(hy)));
    hi = *(unsigned*)&H;
    lo = *(unsigned*)&L;
}

// ---------------------------------------------------------------------------
__global__ void k_init() {
    int i = blockIdx.x * blockDim.x + threadIdx.x;
    if (i < BB * HH) {
        g_h0H[i] = __float2bfloat16(0.f);
        g_h0L[i] = __float2bfloat16(0.f);
        g_c[i] = 0.f;
    }
    if (i < (MPAD - TT * BB) * HH) {
        size_t p = (size_t)TT * BB * HH + i;
        g_hsH[p] = __float2bfloat16(0.f);
        g_hsL[p] = __float2bfloat16(0.f);
    }
}

// ctx[b,h] = sum_l features[b,l,h]; grid (64 batches, 4 h-chunks)
__global__ void k_ctx(const float* __restrict__ features) {
    int b = blockIdx.x;
    int h = blockIdx.y * 256 + threadIdx.x;
    const float* p = features + (size_t)b * 64 * HH + h;
    float s = 0.f;
#pragma unroll 8
    for (int l = 0; l < 64; l++) s += p[(size_t)l * HH];
    bf hi = __float2bfloat16(s);
    g_ctxH[b * HH + h] = hi;
    g_ctxL[b * HH + h] = __float2bfloat16(s - __bfloat162float(hi));
}

__global__ void k_emb(const float* __restrict__ embed, const int* __restrict__ captions) {
    int v = blockIdx.x * blockDim.x + threadIdx.x;
    int m = v >> 7;
    int e4 = (v & 127) << 2;
    int t = m / 64, b = m % 64;
    int cap = captions[b * 32 + t];
    float4 val = *(const float4*)(embed + (size_t)cap * EE + e4);
    uint2 h, l;
    split2(val.x, val.y, h.x, l.x);
    split2(val.z, val.w, h.y, l.y);
    ((uint2*)g_embH)[((size_t)m * EE + e4) >> 2] = h;
    ((uint2*)g_embL)[((size_t)m * EE + e4) >> 2] = l;
}

// ---------------------------------------------------------------------------
// bf16x3 GEMM, A pre-split hi/lo, B RAW FP32 split in-loop.
// BM=64, BN=128, BK=16, 2-stage. Used for gbias (MODE 0) and gx (MODE 1).
// Stage (words): AH[64][12]@0 | AL@768 | Bf32[128][20]@1536  (4096 w = 16 KB)
template<int MODE>
__global__ __launch_bounds__(256) void k_mm(
    const bf* __restrict__ AH, const bf* __restrict__ AL, int lda,
    const float* __restrict__ B, int ldb,
    float* __restrict__ C, int ldc, int K,
    const float* __restrict__ bias1, const float* __restrict__ bias2,
    const float* __restrict__ addM)
{
    __shared__ unsigned sm[2][4096];
    const int tid = threadIdx.x;
    const int wid = tid >> 5, lane = tid & 31, g = lane >> 2, tig = lane & 3;
    const int wm = (wid & 1) * 32, wn = (wid >> 1) * 32;
    const int bm = blockIdx.y * 64, bn = blockIdx.x * 128;

    // copy tasks: A 256 (1/thread, 32B/slab), B 512 (2/thread, 64B/slab)
    const char* csrc[3];
    int cword[3], cstep[3];
    {
        int row = tid >> 2, sel = (tid >> 1) & 1, chunk = tid & 1;
        csrc[0] = (const char*)((sel ? AL : AH) + (size_t)(bm + row) * lda + chunk * 8);
        cword[0] = sel * 768 + row * 12 + chunk * 4;
        cstep[0] = 32;
    }
#pragma unroll
    for (int q = 1; q < 3; q++) {
        int j = tid + (q - 1) * 256;
        int row = j >> 2, chunk = j & 3;
        csrc[q] = (const char*)(B + (size_t)(bn + row) * ldb + chunk * 4);
        cword[q] = 1536 + row * 20 + chunk * 4;
        cstep[q] = 64;
    }

    float acc[2][4][4] = {};
#pragma unroll
    for (int q = 0; q < 3; q++) CP16(s2u(&sm[0][cword[q]]), csrc[q]);
    CP_COMMIT();

    const int KT = K >> 4;
    for (int kt = 0; kt < KT; kt++) {
        const int cur = kt & 1, nxt = cur ^ 1;
        CP_WAIT0();
        __syncthreads();
        if (kt + 1 < KT) {
#pragma unroll
            for (int q = 0; q < 3; q++)
                CP16(s2u(&sm[nxt][cword[q]]), csrc[q] + (kt + 1) * cstep[q]);
            CP_COMMIT();
        }
        const unsigned* AHs = sm[cur];
        const unsigned* ALs = AHs + 768;
        const float* Bf = (const float*)(AHs + 1536);

        unsigned afH[2][4], afL[2][4];
#pragma unroll
        for (int mt = 0; mt < 2; mt++) {
            int r = (wm + mt * 16 + g) * 12;
            afH[mt][0] = AHs[r + tig];     afH[mt][1] = AHs[r + 96 + tig];
            afH[mt][2] = AHs[r + tig + 4]; afH[mt][3] = AHs[r + 96 + tig + 4];
            afL[mt][0] = ALs[r + tig];     afL[mt][1] = ALs[r + 96 + tig];
            afL[mt][2] = ALs[r + tig + 4]; afL[mt][3] = ALs[r + 96 + tig + 4];
        }
#pragma unroll
        for (int nt = 0; nt < 4; nt++) {
            int n = (wn + nt * 8 + g) * 20;
            float2 f0 = *(const float2*)(Bf + n + 2 * tig);
            float2 f1 = *(const float2*)(Bf + n + 2 * tig + 8);
            unsigned bH[2], bL[2];
            split2(f0.x, f0.y, bH[0], bL[0]);
            split2(f1.x, f1.y, bH[1], bL[1]);
#pragma unroll
            for (int mt = 0; mt < 2; mt++) {
                mma_bf16(acc[mt][nt], afL[mt], bH);
                mma_bf16(acc[mt][nt], afH[mt], bL);
                mma_bf16(acc[mt][nt], afH[mt], bH);
            }
        }
    }

#pragma unroll
    for (int mt = 0; mt < 2; mt++) {
#pragma unroll
        for (int nt = 0; nt < 4; nt++) {
            int r0 = bm + wm + mt * 16 + g, r1 = r0 + 8;
            int n0 = bn + wn + nt * 8 + 2 * tig;
            float2 v01 = make_float2(acc[mt][nt][0], acc[mt][nt][1]);
            float2 v23 = make_float2(acc[mt][nt][2], acc[mt][nt][3]);
            if (MODE == 0) {
                float2 x = *(const float2*)(bias1 + n0);
                float2 y = *(const float2*)(bias2 + n0);
                v01.x += x.x + y.x; v01.y += x.y + y.y;
                v23.x += x.x + y.x; v23.y += x.y + y.y;
            }
            if (MODE == 1) {
                float2 x = *(const float2*)(addM + (size_t)(r0 & 63) * GG + n0);
                float2 y = *(const float2*)(addM + (size_t)(r1 & 63) * GG + n0);
                v01.x += x.x; v01.y += x.y;
                v23.x += y.x; v23.y += y.y;
            }
            *(float2*)(C + (size_t)r0 * ldc + n0) = v01;
            *(float2*)(C + (size_t)r1 * ldc + n0) = v23;
        }
    }
}

// ---------------------------------------------------------------------------
// Recurrent step, 3-stage pipeline; W_hh loaded RAW FP32, split in-loop.
// Stage (words): AH[64][12]@0 | AL@768 | Bf32[32][20]@1536  (2176 w)
#define ST_W 2176

__global__ __launch_bounds__(256) void k_step(const bf* __restrict__ AH_,
                                              const bf* __restrict__ AL_,
                                              const float* __restrict__ Whh, int t) {
    __shared__ unsigned sm[3 * ST_W];
    __shared__ float sg[64][33];
    const int tid = threadIdx.x;
    const int wid = tid >> 5, lane = tid & 31, g = lane >> 2, tig = lane & 3;
    const int wm = (wid & 1) * 32, wn = (wid >> 1) * 8;
    const int jj0 = blockIdx.x * 8;

    const bf* asrc;
    int acw;
    {
        int row = tid >> 2, sel = (tid >> 1) & 1, chunk = tid & 1;
        asrc = (sel ? AL_ : AH_) + (size_t)row * HH + chunk * 8;
        acw = sel * 768 + row * 12 + chunk * 4;
    }
    const float* bsrc = nullptr;
    int bcw = 0;
    if (tid < 128) {
        int br = tid >> 2, bc = tid & 3;      // 32 rows x 4 chunks of 4 floats
        int wrow = (br >> 3) * HH + jj0 + (br & 7);
        bsrc = Whh + (size_t)wrow * HH + bc * 4;
        bcw = 1536 + br * 20 + bc * 4;
    }

    float acc[2][4] = {};
#pragma unroll
    for (int s = 0; s < 2; s++) {
        CP16(s2u(&sm[s * ST_W + acw]), asrc + s * 16);
        if (tid < 128) CP16(s2u(&sm[s * ST_W + bcw]), bsrc + s * 16);
        CP_COMMIT();
    }

    const int KT = HH >> 4;
    int buf = 0;
    for (int kt = 0; kt < KT; kt++) {
        CP_WAIT1();
        __syncthreads();
        if (kt + 2 < KT) {
            int s = (buf + 2) % 3;
            CP16(s2u(&sm[s * ST_W + acw]), asrc + (kt + 2) * 16);
            if (tid < 128) CP16(s2u(&sm[s * ST_W + bcw]), bsrc + (kt + 2) * 16);
            CP_COMMIT();
        } else {
            CP_COMMIT();
        }

        const unsigned* AHs = sm + buf * ST_W;
        const unsigned* ALs = AHs + 768;
        const float* Bf = (const float*)(AHs + 1536);

        unsigned afH[2][4], afL[2][4], bH[2], bL[2];
#pragma unroll
        for (int mt = 0; mt < 2; mt++) {
            int r = (wm + mt * 16 + g) * 12;
            afH[mt][0] = AHs[r + tig];     afH[mt][1] = AHs[r + 96 + tig];
            afH[mt][2] = AHs[r + tig + 4]; afH[mt][3] = AHs[r + 96 + tig + 4];
            afL[mt][0] = ALs[r + tig];     afL[mt][1] = ALs[r + 96 + tig];
            afL[mt][2] = ALs[r + tig + 4]; afL[mt][3] = ALs[r + 96 + tig + 4];
        }
        int n = (wn + g) * 20;
        float2 f0 = *(const float2*)(Bf + n + 2 * tig);
        float2 f1 = *(const float2*)(Bf + n + 2 * tig + 8);
        split2(f0.x, f0.y, bH[0], bL[0]);
        split2(f1.x, f1.y, bH[1], bL[1]);
#pragma unroll
        for (int mt = 0; mt < 2; mt++) {
            mma_bf16(acc[mt], afL[mt], bH);
            mma_bf16(acc[mt], afH[mt], bL);
            mma_bf16(acc[mt], afH[mt], bH);
        }
        buf = (buf + 1) % 3;
    }

#pragma unroll
    for (int mt = 0; mt < 2; mt++)
#pragma unroll
        for (int q = 0; q < 4; q++) {
            int r = wm + mt * 16 + g + ((q >> 1) * 8);
            int j = wn + 2 * tig + (q & 1);
            sg[r][j] = acc[mt][q];
        }
    __syncthreads();

    const float* __restrict__ gx = g_gx + (size_t)t * 64 * GG;
    for (int u = tid; u < 512; u += 256) {
        int b = u >> 3, hh = u & 7;
        size_t gbase = (size_t)b * GG + jj0 + hh;
        float gi = sg[b][0 * 8 + hh] + gx[gbase];
        float gf = sg[b][1 * 8 + hh] + gx[gbase + HH];
        float gg = sg[b][2 * 8 + hh] + gx[gbase + 2 * HH];
        float go = sg[b][3 * 8 + hh] + gx[gbase + 3 * HH];
        int ci = b * HH + jj0 + hh;
        float cOld = g_c[ci];
        float si = 1.f / (1.f + expf(-gi));
        float sf = 1.f / (1.f + expf(-gf));
        float so = 1.f / (1.f + expf(-go));
        float cN = sf * cOld + si * tanhf(gg);
        float hN = so * tanhf(cN);
        g_c[ci] = cN;
        size_t hidx = ((size_t)t * 64 + b) * HH + jj0 + hh;
        bf hb = __float2bfloat16(hN);
        g_hsH[hidx] = hb;
        g_hsL[hidx] = __float2bfloat16(hN - __bfloat162float(hb));
    }
}

// ---------------------------------------------------------------------------
// Logits GEMM (R14 proven): BM=128, BN=128, warp 32x64, 3-stage, B fp32 in-loop.
#define LG_STG 5632
#define SMEM_LG3 (3 * LG_STG * 4)    // 66 KB

__global__ __launch_bounds__(256, 2) void k_logits3(const float* __restrict__ linW,
                                                    const float* __restrict__ lin_b,
                                                    float* __restrict__ out) {
    extern __shared__ unsigned sm[];
    const int tid = threadIdx.x;
    const int wid = tid >> 5, lane = tid & 31, g = lane >> 2, tig = lane & 3;
    const int wm = (wid & 3) * 32, wn = (wid >> 2) * 64;
    const int bm = blockIdx.x * 128, bn = blockIdx.y * 128;

    const char* csrc[4];
    int cword[4], cstep[4];
#pragma unroll
    for (int q = 0; q < 4; q++) {
        int i = tid + q * 256;
        if (i < 512) {
            int row = i >> 2, sel = (i >> 1) & 1, chunk = i & 1;
            csrc[q] = (const char*)((sel ? g_hsL : g_hsH) + (size_t)(bm + row) * HH + chunk * 8);
            cword[q] = sel * 1536 + row * 12 + chunk * 4;
            cstep[q] = 32;
        } else {
            int j = i - 512;
            int row = j >> 2, chunk = j & 3;
            csrc[q] = (const char*)(linW + (size_t)(bn + row) * HH + chunk * 4);
            cword[q] = 3072 + row * 20 + chunk * 4;
            cstep[q] = 64;
        }
    }

    float acc[2][8][4] = {};

#pragma unroll
    for (int s = 0; s < 2; s++) {
#pragma unroll
        for (int q = 0; q < 4; q++)
            CP16(s2u(&sm[s * LG_STG + cword[q]]), csrc[q] + s * cstep[q]);
        CP_COMMIT();
    }

    const int KT = HH >> 4;
    int buf = 0;
    for (int kt = 0; kt < KT; kt++) {
        CP_WAIT1();
        __syncthreads();
        if (kt + 2 < KT) {
            int s = (buf + 2) % 3;
#pragma unroll
            for (int q = 0; q < 4; q++)
                CP16(s2u(&sm[s * LG_STG + cword[q]]), csrc[q] + (kt + 2) * cstep[q]);
            CP_COMMIT();
        } else {
            CP_COMMIT();
        }

        const unsigned* AHs = sm + buf * LG_STG;
        const unsigned* ALs = AHs + 1536;
        const float* Bf = (const float*)(AHs + 3072);

        unsigned aH[2][4], aL[2][4];
#pragma unroll
        for (int mt = 0; mt < 2; mt++) {
            int r = (wm + mt * 16 + g) * 12;
            aH[mt][0] = AHs[r + tig];     aH[mt][1] = AHs[r + 96 + tig];
            aH[mt][2] = AHs[r + tig + 4]; aH[mt][3] = AHs[r + 96 + tig + 4];
            aL[mt][0] = ALs[r + tig];     aL[mt][1] = ALs[r + 96 + tig];
            aL[mt][2] = ALs[r + tig + 4]; aL[mt][3] = ALs[r + 96 + tig + 4];
        }
#pragma unroll
        for (int nt = 0; nt < 8; nt++) {
            int n = (wn + nt * 8 + g) * 20;
            float2 f0 = *(const float2*)(Bf + n + 2 * tig);
            float2 f1 = *(const float2*)(Bf + n + 2 * tig + 8);
            unsigned bH[2], bL[2];
            split2(f0.x, f0.y, bH[0], bL[0]);
            split2(f1.x, f1.y, bH[1], bL[1]);
#pragma unroll
            for (int mt = 0; mt < 2; mt++) {
                mma_bf16(acc[mt][nt], aL[mt], bH);
                mma_bf16(acc[mt][nt], aH[mt], bL);
                mma_bf16(acc[mt][nt], aH[mt], bH);
            }
        }
        buf = (buf + 1) % 3;
    }

#pragma unroll
    for (int mt = 0; mt < 2; mt++) {
#pragma unroll
        for (int q2 = 0; q2 < 2; q2++) {
            int m = bm + wm + mt * 16 + g + q2 * 8;
            if (m >= TT * BB) continue;
            float* orow = out + (size_t)m * VV + bn;
#pragma unroll
            for (int nt = 0; nt < 8; nt++) {
                int n0 = wn + nt * 8 + 2 * tig;
                float2 bb = *(const float2*)(lin_b + bn + n0);
                float2 v = make_float2(acc[mt][nt][q2 * 2] + bb.x,
                                       acc[mt][nt][q2 * 2 + 1] + bb.y);
                *(float2*)(orow + n0) = v;
            }
        }
    }
}

// ---------------------------------------------------------------------------
extern "C" void kernel_launch(void* const* d_in, const int* in_sizes, int n_in,
                              void* d_out, int out_size) {
    const float* features = (const float*)d_in[0];
    const int*   captions = (const int*)d_in[1];
    const float* embed    = (const float*)d_in[3];
    const float* W_ih     = (const float*)d_in[4];
    const float* W_hh     = (const float*)d_in[5];
    const float* b_ih     = (const float*)d_in[6];
    const float* b_hh     = (const float*)d_in[7];
    const float* lin_W    = (const float*)d_in[10];
    const float* lin_b    = (const float*)d_in[11];
    float* out = (float*)d_out;

    bf *p_ctxH, *p_ctxL, *p_embH, *p_embL, *p_hsH, *p_hsL, *p_h0H, *p_h0L;
    float *p_gbias, *p_gx;
    cudaGetSymbolAddress((void**)&p_ctxH, g_ctxH);
    cudaGetSymbolAddress((void**)&p_ctxL, g_ctxL);
    cudaGetSymbolAddress((void**)&p_embH, g_embH);
    cudaGetSymbolAddress((void**)&p_embL, g_embL);
    cudaGetSymbolAddress((void**)&p_hsH, g_hsH);
    cudaGetSymbolAddress((void**)&p_hsL, g_hsL);
    cudaGetSymbolAddress((void**)&p_h0H, g_h0H);
    cudaGetSymbolAddress((void**)&p_h0L, g_h0L);
    cudaGetSymbolAddress((void**)&p_gbias, g_gbias);
    cudaGetSymbolAddress((void**)&p_gx, g_gx);

    cudaFuncSetAttribute(k_logits3, cudaFuncAttributeMaxDynamicSharedMemorySize, SMEM_LG3);

    k_init<<<(BB * HH + 255) / 256, 256>>>();
    k_ctx<<<dim3(BB, 4), 256>>>(features);
    k_emb<<<(TT * BB * EE / 4 + 255) / 256, 256>>>(embed, captions);
    // gbias = ctx @ W_ih[:,512:]^T + b_ih + b_hh   (W_ih fp32, in-loop split)
    k_mm<0><<<dim3(GG / 128, 1), 256>>>(p_ctxH, p_ctxL, HH,
                                        W_ih + 512, 1536,
                                        p_gbias, GG, HH, b_ih, b_hh, nullptr);
    // gx = emb @ W_ih[:,:512]^T + gbias            (W_ih fp32, in-loop split)
    k_mm<1><<<dim3(GG / 128, TT), 256>>>(p_embH, p_embL, EE,
                                         W_ih, 1536,
                                         p_gx, GG, EE, nullptr, nullptr, p_gbias);
    // 31 recurrent steps (W_hh fp32, in-loop split)
    for (int t = 0; t < TT; t++) {
        const bf* AH = t ? p_hsH + (size_t)(t - 1) * BB * HH : p_h0H;
        const bf* AL = t ? p_hsL + (size_t)(t - 1) * BB * HH : p_h0L;
        k_step<<<128, 256>>>(AH, AL, W_hh, t);
    }
    // logits = hs @ lin_W^T + lin_b (lin_W fp32, in-loop split)
    k_logits3<<<dim3(MPAD / 128, VV / 128), 256, SMEM_LG3>>>(lin_W, lin_b, out);
}